// round 3
// baseline (speedup 1.0000x reference)
#include <cuda_runtime.h>
#include <cuda_bf16.h>

// DWT1D bior2.2 (symmetric) + linear downsample, fused.
// x: [32, 64, 16384] f32 -> out: [32, 192, 8194] f32  (concat[ds, a, d] on ch axis)
//
// a[t] = sum_{m=1..5} DEC_LO[m] * x[refl(2t+1-m)]
// d[t] = sum_{m=1..3} DEC_HI[m] * x[refl(2t+1-m)]
// refl(g) = -1-g if g<0 ; 2N-1-g if g>=N ; g otherwise
// ds[t] = linear interp at src=(t+0.5)*(N/L)-0.5 (fp32, align_corners=False)

#define NN   16384
#define LL   8194
#define TILE 256
#define SMEM_N 528   // need [2*t0-8, 2*t0+511+1] -> span 521; pad to 528
#define ROWS 2048    // 32 * 64

__global__ __launch_bounds__(TILE) void dwt1d_fused_kernel(
    const float* __restrict__ x, float* __restrict__ out)
{
    __shared__ float sm[SMEM_N];
    const int row = blockIdx.y;               // b*64 + c
    const int t0  = blockIdx.x * TILE;
    const int gbase = 2 * t0 - 8;
    const float* __restrict__ xr = x + (size_t)row * NN;

    // Coalesced load with symmetric reflection applied at the edges.
    for (int s = threadIdx.x; s < SMEM_N; s += TILE) {
        int g = gbase + s;
        if (g < 0)        g = -1 - g;
        else if (g >= NN) g = 2 * NN - 1 - g;
        sm[s] = __ldg(xr + g);
    }
    __syncthreads();

    const int j = threadIdx.x;
    const int t = t0 + j;
    if (t >= LL) return;

    // ---- DWT taps (local index of x[2t] in smem is 2j+8) ----
    const int c = 2 * j + 8;
    const float x0 = sm[c];      // x[2t]
    const float x1 = sm[c - 1];  // x[2t-1]
    const float x2 = sm[c - 2];  // x[2t-2]
    const float x3 = sm[c - 3];  // x[2t-3]
    const float x4 = sm[c - 4];  // x[2t-4]

    const float LO1 = -0.1767766952966369f;  // DEC_LO[1] == DEC_LO[5]
    const float LO2 =  0.3535533905932738f;  // DEC_LO[2] == DEC_LO[4]
    const float LO3 =  1.0606601717798212f;  // DEC_LO[3]
    const float HI1 =  0.3535533905932738f;  // DEC_HI[1] == DEC_HI[3]
    const float HI2 = -0.7071067811865476f;  // DEC_HI[2]

    const float a = LO1 * (x0 + x4) + LO2 * (x1 + x3) + LO3 * x2;
    const float d = HI1 * (x0 + x2) + HI2 * x1;

    // ---- linear downsample (matches fp32 jnp arithmetic) ----
    const float SCALE = (float)(16384.0 / 8194.0);
    float src = ((float)t + 0.5f) * SCALE - 0.5f;
    src = fminf(fmaxf(src, 0.0f), (float)(NN - 1));
    int   i0 = (int)floorf(src);
    int   i1 = min(i0 + 1, NN - 1);
    float w  = src - (float)i0;
    // i0,i1 provably within the loaded smem window (see analysis).
    const float ds = sm[i0 - gbase] * (1.0f - w) + sm[i1 - gbase] * w;

    // ---- store: out[b, {c, 64+c, 128+c}, t] ----
    const int b  = row >> 6;
    const int ch = row & 63;
    const size_t base = ((size_t)b * 192 + ch) * LL + t;
    out[base]                    = ds;
    out[base + (size_t)64 * LL]  = a;
    out[base + (size_t)128 * LL] = d;
}

extern "C" void kernel_launch(void* const* d_in, const int* in_sizes, int n_in,
                              void* d_out, int out_size)
{
    const float* x = (const float*)d_in[0];
    float* out = (float*)d_out;
    dim3 grid((LL + TILE - 1) / TILE, ROWS);
    dwt1d_fused_kernel<<<grid, TILE>>>(x, out);
}

// round 4
// speedup vs baseline: 1.3095x; 1.3095x over previous
#include <cuda_runtime.h>
#include <cuda_bf16.h>

// DWT1D bior2.2 (symmetric) + linear downsample, fused. 4 outputs/thread.
// x: [32, 64, 16384] f32 -> out: [32, 192, 8194] f32 (concat[ds, a, d] on ch)

#define NN      16384
#define LL      8194
#define THREADS 256
#define TILE_T  1024              // outputs per block
#define NTILES  9                 // ceil(8194/1024)
#define SMEM_N  2056              // window [2*t0-8 .. 2*t0+2047]

__global__ __launch_bounds__(THREADS) void dwt1d_fused_kernel(
    const float* __restrict__ x, float* __restrict__ out)
{
    __shared__ float sm[SMEM_N];
    const int tid  = threadIdx.x;
    const int row  = blockIdx.y;              // b*64 + c
    const int bx   = blockIdx.x;
    const int t0   = bx * TILE_T;
    const int gbase = 2 * t0 - 8;
    const float* __restrict__ xr = x + (size_t)row * NN;

    if (bx > 0 && bx < NTILES - 1) {
        // Interior: no reflection possible; gbase is 16B-aligned.
        const float4* __restrict__ xr4 = (const float4*)(xr + gbase);
        float4* sm4 = (float4*)sm;
        sm4[tid]       = __ldg(xr4 + tid);
        sm4[tid + 256] = __ldg(xr4 + tid + 256);
        if (tid < (SMEM_N / 4) - 512)          // 514 total float4s
            sm4[tid + 512] = __ldg(xr4 + tid + 512);
    } else {
        // Edge tiles: scalar with symmetric reflection.
        for (int s = tid; s < SMEM_N; s += THREADS) {
            int g = gbase + s;
            if (g < 0)        g = -1 - g;
            else if (g >= NN) g = 2 * NN - 1 - g;
            sm[s] = __ldg(xr + g);
        }
    }
    __syncthreads();

    // Thread computes t = tbase + {0,1,2,3}. Local idx of x[2t] is 8*tid+8+2k.
    const int tbase = t0 + 4 * tid;
    const float4* s4 = (const float4*)sm;
    const float4 A = s4[2 * tid + 1];   // sm[8tid+4 .. 8tid+7]
    const float4 B = s4[2 * tid + 2];   // sm[8tid+8 .. 8tid+11]
    const float4 C = s4[2 * tid + 3];   // sm[8tid+12 .. 8tid+15]
    float f[12] = {A.x, A.y, A.z, A.w, B.x, B.y, B.z, B.w, C.x, C.y, C.z, C.w};
    // f[i] = sm[8tid+4+i]; output k: x4=f[2k] x3=f[2k+1] x2=f[2k+2] x1=f[2k+3] x0=f[2k+4]

    const float LO1 = -0.1767766952966369f;
    const float LO2 =  0.3535533905932738f;
    const float LO3 =  1.0606601717798212f;
    const float HI1 =  0.3535533905932738f;
    const float HI2 = -0.7071067811865476f;
    const float SCALE = (float)(16384.0 / 8194.0);

    float av[4], dv[4], dsv[4];
    #pragma unroll
    for (int k = 0; k < 4; k++) {
        const float x4 = f[2*k], x3 = f[2*k+1], x2 = f[2*k+2], x1 = f[2*k+3], x0 = f[2*k+4];
        av[k] = LO1 * (x0 + x4) + LO2 * (x1 + x3) + LO3 * x2;
        dv[k] = HI1 * (x0 + x2) + HI2 * x1;

        float src = ((float)(tbase + k) + 0.5f) * SCALE - 0.5f;
        src = fminf(fmaxf(src, 0.0f), (float)(NN - 1));
        int   i0 = (int)floorf(src);
        int   i1 = min(i0 + 1, NN - 1);
        float w  = src - (float)i0;
        // i0,i1 - gbase proven within [2, 8*tid+15] -> in-window.
        dsv[k] = sm[i0 - gbase] * (1.0f - w) + sm[i1 - gbase] * w;
    }

    const int b  = row >> 6;
    const int ch = row & 63;
    float* o0 = out + ((size_t)b * 192 + ch) * LL + tbase;  // ds
    float* o1 = o0 + (size_t)64 * LL;                       // a
    float* o2 = o0 + (size_t)128 * LL;                      // d

    if (bx < NTILES - 1) {
        // tbase even, row base even -> 8B aligned: float2 stores legal.
        ((float2*)o0)[0] = make_float2(dsv[0], dsv[1]);
        ((float2*)o0)[1] = make_float2(dsv[2], dsv[3]);
        ((float2*)o1)[0] = make_float2(av[0], av[1]);
        ((float2*)o1)[1] = make_float2(av[2], av[3]);
        ((float2*)o2)[0] = make_float2(dv[0], dv[1]);
        ((float2*)o2)[1] = make_float2(dv[2], dv[3]);
    } else {
        #pragma unroll
        for (int k = 0; k < 4; k++) {
            if (tbase + k < LL) {
                o0[k] = dsv[k];
                o1[k] = av[k];
                o2[k] = dv[k];
            }
        }
    }
}

extern "C" void kernel_launch(void* const* d_in, const int* in_sizes, int n_in,
                              void* d_out, int out_size)
{
    const float* x = (const float*)d_in[0];
    float* out = (float*)d_out;
    dim3 grid(NTILES, 2048);
    dwt1d_fused_kernel<<<grid, THREADS>>>(x, out);
}

// round 7
// speedup vs baseline: 1.6119x; 1.2309x over previous
#include <cuda_runtime.h>
#include <cuda_bf16.h>

// DWT1D bior2.2 (symmetric) + linear downsample, fused. 4 outputs/thread.
// x: [32, 64, 16384] f32 -> out: [32, 192, 8194] f32 (concat[ds, a, d] on ch)
// Interp gather done in registers (e = 2t - i0 in [0,6]) via SEL mux -> no
// bank-conflicted scalar LDS.

#define NN      16384
#define LL      8194
#define THREADS 256
#define TILE_T  1024
#define NTILES  9
#define SMEM_N  2056   // window [2*t0-8 .. 2*t0+2047]

// returns a_e for e in [0,6] via 3-level SEL tree
__device__ __forceinline__ float sel7(float a0, float a1, float a2, float a3,
                                      float a4, float a5, float a6, int e)
{
    float b0 = (e & 1) ? a1 : a0;
    float b2 = (e & 1) ? a3 : a2;
    float b4 = (e & 1) ? a5 : a4;
    float c0 = (e & 2) ? b2 : b0;
    float c4 = (e & 2) ? a6 : b4;   // e&2 with e>=6 only for e=6 (even) -> a6
    return (e & 4) ? c4 : c0;
}

__global__ __launch_bounds__(THREADS) void dwt1d_fused_kernel(
    const float* __restrict__ x, float* __restrict__ out)
{
    __shared__ float sm[SMEM_N];
    const int tid  = threadIdx.x;
    const int row  = blockIdx.y;              // b*64 + c
    const int bx   = blockIdx.x;
    const int t0   = bx * TILE_T;
    const int gbase = 2 * t0 - 8;
    const float* __restrict__ xr = x + (size_t)row * NN;

    if (bx > 0 && bx < NTILES - 1) {
        const float4* __restrict__ xr4 = (const float4*)(xr + gbase);
        float4* sm4 = (float4*)sm;
        sm4[tid]       = __ldg(xr4 + tid);
        sm4[tid + 256] = __ldg(xr4 + tid + 256);
        if (tid < (SMEM_N / 4) - 512)
            sm4[tid + 512] = __ldg(xr4 + tid + 512);
    } else {
        for (int s = tid; s < SMEM_N; s += THREADS) {
            int g = gbase + s;
            if (g < 0)        g = -1 - g;
            else if (g >= NN) g = 2 * NN - 1 - g;
            sm[s] = __ldg(xr + g);
        }
    }
    __syncthreads();

    const int tbase = t0 + 4 * tid;
    if (tbase >= LL) return;

    // g[i] = sm[8*tid + i] = x[gbase + 8*tid + i];  x[2t] for output k is g[2k+8]
    const float4* s4 = (const float4*)sm;
    const float4 D = s4[2 * tid];
    const float4 A = s4[2 * tid + 1];
    const float4 B = s4[2 * tid + 2];
    const float4 C = s4[2 * tid + 3];
    const float g[16] = {D.x, D.y, D.z, D.w, A.x, A.y, A.z, A.w,
                         B.x, B.y, B.z, B.w, C.x, C.y, C.z, C.w};

    const float LO1 = -0.1767766952966369f;
    const float LO2 =  0.3535533905932738f;
    const float LO3 =  1.0606601717798212f;
    const float HI1 =  0.3535533905932738f;
    const float HI2 = -0.7071067811865476f;
    const float SCALE = (float)(16384.0 / 8194.0);

    float av[4], dv[4], dsv[4];
    #pragma unroll
    for (int k = 0; k < 4; k++) {
        const float x0 = g[2*k + 8], x1 = g[2*k + 7], x2 = g[2*k + 6],
                    x3 = g[2*k + 5], x4 = g[2*k + 4];
        av[k] = LO1 * (x0 + x4) + LO2 * (x1 + x3) + LO3 * x2;
        dv[k] = HI1 * (x0 + x2) + HI2 * x1;

        const int t = tbase + k;
        float src = ((float)t + 0.5f) * SCALE - 0.5f;   // in [0.4996, 16380.5] -> no clamp
        int   i0  = (int)floorf(src);
        float w   = src - (float)i0;
        int   e   = 2 * t - i0;                          // in [0, 6]
        // lo = g[2k+8-e], hi = g[2k+9-e]
        float lo = sel7(g[2*k+8], g[2*k+7], g[2*k+6], g[2*k+5],
                        g[2*k+4], g[2*k+3], g[2*k+2], e);
        float hi = sel7(g[2*k+9], g[2*k+8], g[2*k+7], g[2*k+6],
                        g[2*k+5], g[2*k+4], g[2*k+3], e);
        dsv[k] = lo * (1.0f - w) + hi * w;
    }

    const int b  = row >> 6;
    const int ch = row & 63;
    float* o0 = out + ((size_t)b * 192 + ch) * LL + tbase;  // ds
    float* o1 = o0 + (size_t)64 * LL;                       // a
    float* o2 = o0 + (size_t)128 * LL;                      // d

    if (bx < NTILES - 1) {
        if ((row & 1) == 0) {
            // row base elem offset = 8194*row even*... -> 16B aligned when row even
            *(float4*)o0 = make_float4(dsv[0], dsv[1], dsv[2], dsv[3]);
            *(float4*)o1 = make_float4(av[0], av[1], av[2], av[3]);
            *(float4*)o2 = make_float4(dv[0], dv[1], dv[2], dv[3]);
        } else {
            ((float2*)o0)[0] = make_float2(dsv[0], dsv[1]);
            ((float2*)o0)[1] = make_float2(dsv[2], dsv[3]);
            ((float2*)o1)[0] = make_float2(av[0], av[1]);
            ((float2*)o1)[1] = make_float2(av[2], av[3]);
            ((float2*)o2)[0] = make_float2(dv[0], dv[1]);
            ((float2*)o2)[1] = make_float2(dv[2], dv[3]);
        }
    } else {
        #pragma unroll
        for (int k = 0; k < 4; k++) {
            if (tbase + k < LL) {
                o0[k] = dsv[k];
                o1[k] = av[k];
                o2[k] = dv[k];
            }
        }
    }
}

extern "C" void kernel_launch(void* const* d_in, const int* in_sizes, int n_in,
                              void* d_out, int out_size)
{
    const float* x = (const float*)d_in[0];
    float* out = (float*)d_out;
    dim3 grid(NTILES, 2048);
    dwt1d_fused_kernel<<<grid, THREADS>>>(x, out);
}

// round 11
// speedup vs baseline: 1.9988x; 1.2401x over previous
#include <cuda_runtime.h>
#include <cuda_bf16.h>

// DWT1D bior2.2 (symmetric) + linear downsample, fused. 4 outputs/thread.
// x: [32, 64, 16384] f32 -> out: [32, 192, 8194] f32 (concat[ds, a, d] on ch)
// No shared memory: each thread loads its 16-float window with 4 LDG.128;
// interp gather resolved in registers via SEL mux (e = 2t - i0 in [0,6]).

#define NN      16384
#define LL      8194
#define THREADS 256
#define TILE_T  1024
#define NTILES  9

__device__ __forceinline__ float sel7(float a0, float a1, float a2, float a3,
                                      float a4, float a5, float a6, int e)
{
    float b0 = (e & 1) ? a1 : a0;
    float b2 = (e & 1) ? a3 : a2;
    float b4 = (e & 1) ? a5 : a4;
    float c0 = (e & 2) ? b2 : b0;
    float c4 = (e & 2) ? a6 : b4;
    return (e & 4) ? c4 : c0;
}

__global__ __launch_bounds__(THREADS) void dwt1d_fused_kernel(
    const float* __restrict__ x, float* __restrict__ out)
{
    const int tid  = threadIdx.x;
    const int row  = blockIdx.y;              // b*64 + c
    const int bx   = blockIdx.x;
    const int t0   = bx * TILE_T;
    const int tbase = t0 + 4 * tid;
    if (tbase >= LL) return;

    const float* __restrict__ xr = x + (size_t)row * NN;
    const int g0 = 2 * tbase - 8;             // window start; == 0 mod 8 -> 32B aligned

    // g[i] = x[refl(g0 + i)], i in [0,16)
    float g[16];
    if (g0 >= 0 && g0 + 15 < NN) {
        const float4* __restrict__ p = (const float4*)(xr + g0);
        float4 A = __ldg(p + 0), B = __ldg(p + 1), C = __ldg(p + 2), D = __ldg(p + 3);
        g[0]=A.x; g[1]=A.y; g[2]=A.z; g[3]=A.w;
        g[4]=B.x; g[5]=B.y; g[6]=B.z; g[7]=B.w;
        g[8]=C.x; g[9]=C.y; g[10]=C.z; g[11]=C.w;
        g[12]=D.x; g[13]=D.y; g[14]=D.z; g[15]=D.w;
    } else {
        #pragma unroll
        for (int i = 0; i < 16; i++) {
            int idx = g0 + i;
            if (idx < 0)        idx = -1 - idx;
            else if (idx >= NN) idx = 2 * NN - 1 - idx;
            g[i] = __ldg(xr + idx);
        }
    }

    const float LO1 = -0.1767766952966369f;
    const float LO2 =  0.3535533905932738f;
    const float LO3 =  1.0606601717798212f;
    const float HI1 =  0.3535533905932738f;
    const float HI2 = -0.7071067811865476f;
    const float SCALE = (float)(16384.0 / 8194.0);

    float av[4], dv[4], dsv[4];
    #pragma unroll
    for (int k = 0; k < 4; k++) {
        const float x0 = g[2*k + 8], x1 = g[2*k + 7], x2 = g[2*k + 6],
                    x3 = g[2*k + 5], x4 = g[2*k + 4];
        av[k] = LO1 * (x0 + x4) + LO2 * (x1 + x3) + LO3 * x2;
        dv[k] = HI1 * (x0 + x2) + HI2 * x1;

        const int t = tbase + k;
        float src = ((float)t + 0.5f) * SCALE - 0.5f;   // in [0.4996, 16380.5]
        int   i0  = (int)floorf(src);
        float w   = src - (float)i0;
        int   e   = 2 * t - i0;                          // in [0, 6]
        float lo = sel7(g[2*k+8], g[2*k+7], g[2*k+6], g[2*k+5],
                        g[2*k+4], g[2*k+3], g[2*k+2], e);
        float hi = sel7(g[2*k+9], g[2*k+8], g[2*k+7], g[2*k+6],
                        g[2*k+5], g[2*k+4], g[2*k+3], e);
        dsv[k] = lo * (1.0f - w) + hi * w;
    }

    const int b  = row >> 6;
    const int ch = row & 63;
    float* o0 = out + ((size_t)b * 192 + ch) * LL + tbase;  // ds
    float* o1 = o0 + (size_t)64 * LL;                       // a
    float* o2 = o0 + (size_t)128 * LL;                      // d

    if (tbase + 3 < LL) {
        if ((row & 1) == 0) {
            // row elem offset 8194*row + tbase == 0 mod 4 -> 16B aligned
            *(float4*)o0 = make_float4(dsv[0], dsv[1], dsv[2], dsv[3]);
            *(float4*)o1 = make_float4(av[0], av[1], av[2], av[3]);
            *(float4*)o2 = make_float4(dv[0], dv[1], dv[2], dv[3]);
        } else {
            ((float2*)o0)[0] = make_float2(dsv[0], dsv[1]);
            ((float2*)o0)[1] = make_float2(dsv[2], dsv[3]);
            ((float2*)o1)[0] = make_float2(av[0], av[1]);
            ((float2*)o1)[1] = make_float2(av[2], av[3]);
            ((float2*)o2)[0] = make_float2(dv[0], dv[1]);
            ((float2*)o2)[1] = make_float2(dv[2], dv[3]);
        }
    } else {
        #pragma unroll
        for (int k = 0; k < 4; k++) {
            if (tbase + k < LL) {
                o0[k] = dsv[k];
                o1[k] = av[k];
                o2[k] = dv[k];
            }
        }
    }
}

extern "C" void kernel_launch(void* const* d_in, const int* in_sizes, int n_in,
                              void* d_out, int out_size)
{
    const float* x = (const float*)d_in[0];
    float* out = (float*)d_out;
    dim3 grid(NTILES, 2048);
    dwt1d_fused_kernel<<<grid, THREADS>>>(x, out);
}

// round 15
// speedup vs baseline: 2.0228x; 1.0120x over previous
#include <cuda_runtime.h>
#include <cuda_bf16.h>

// DWT1D bior2.2 (symmetric) + linear downsample, fused. 4 outputs/thread.
// x: [32, 64, 16384] f32 -> out: [32, 192, 8194] f32 (concat[ds, a, d] on ch)
// Zero-redundancy loads: each thread LDG.128-loads only its own 32B; the
// 8-float halo comes from the previous lane via __shfl_up. Lane 0 loads its
// halo directly. Interp gather resolved in registers via SEL mux (e in [0,6]).

#define NN      16384
#define LL      8194
#define THREADS 256
#define TILE_T  1024
#define NTILES  9

__device__ __forceinline__ int refl(int idx)
{
    if (idx < 0)   return -1 - idx;
    if (idx >= NN) return 2 * NN - 1 - idx;
    return idx;
}

__device__ __forceinline__ float sel7(float a0, float a1, float a2, float a3,
                                      float a4, float a5, float a6, int e)
{
    float b0 = (e & 1) ? a1 : a0;
    float b2 = (e & 1) ? a3 : a2;
    float b4 = (e & 1) ? a5 : a4;
    float c0 = (e & 2) ? b2 : b0;
    float c4 = (e & 2) ? a6 : b4;
    return (e & 4) ? c4 : c0;
}

__global__ __launch_bounds__(THREADS) void dwt1d_fused_kernel(
    const float* __restrict__ x, float* __restrict__ out)
{
    const int tid   = threadIdx.x;
    const int lane  = tid & 31;
    const int row   = blockIdx.y;             // b*64 + c
    const int bx    = blockIdx.x;
    const int t0    = bx * TILE_T;
    const int tbase = t0 + 4 * tid;           // may exceed LL in last tile; no return!

    const float* __restrict__ xr = x + (size_t)row * NN;
    const int ob = 2 * tbase;                 // own window start (32B aligned)

    // h[i] = x[refl(ob + i)], i in [0,8)  -- this thread's own 8 floats
    float h[8];
    if (ob + 7 < NN) {
        float4 A = __ldcs((const float4*)(xr + ob));
        float4 B = __ldcs((const float4*)(xr + ob) + 1);
        h[0]=A.x; h[1]=A.y; h[2]=A.z; h[3]=A.w;
        h[4]=B.x; h[5]=B.y; h[6]=B.z; h[7]=B.w;
    } else {
        #pragma unroll
        for (int i = 0; i < 8; i++) h[i] = __ldg(xr + refl(ob + i));
    }

    // Halo g[0..7] = x[refl(ob-8 .. ob-1)] = previous lane's h
    float g[16];
    #pragma unroll
    for (int i = 0; i < 8; i++) {
        g[i]     = __shfl_up_sync(0xffffffffu, h[i], 1);
        g[8 + i] = h[i];
    }
    if (lane == 0) {
        const int hb = ob - 8;
        if (hb >= 0 && hb + 7 < NN) {
            float4 A = __ldcs((const float4*)(xr + hb));
            float4 B = __ldcs((const float4*)(xr + hb) + 1);
            g[0]=A.x; g[1]=A.y; g[2]=A.z; g[3]=A.w;
            g[4]=B.x; g[5]=B.y; g[6]=B.z; g[7]=B.w;
        } else {
            #pragma unroll
            for (int i = 0; i < 8; i++) g[i] = __ldg(xr + refl(hb + i));
        }
    }

    const float LO1 = -0.1767766952966369f;
    const float LO2 =  0.3535533905932738f;
    const float LO3 =  1.0606601717798212f;
    const float HI1 =  0.3535533905932738f;
    const float HI2 = -0.7071067811865476f;
    const float SCALE = (float)(16384.0 / 8194.0);

    float av[4], dv[4], dsv[4];
    #pragma unroll
    for (int k = 0; k < 4; k++) {
        const float x0 = g[2*k + 8], x1 = g[2*k + 7], x2 = g[2*k + 6],
                    x3 = g[2*k + 5], x4 = g[2*k + 4];
        av[k] = LO1 * (x0 + x4) + LO2 * (x1 + x3) + LO3 * x2;
        dv[k] = HI1 * (x0 + x2) + HI2 * x1;

        const int t = tbase + k;
        float src = ((float)t + 0.5f) * SCALE - 0.5f;   // in [0.4996, 16380.5]
        int   i0  = (int)src;                            // == floor (src > 0)
        float w   = src - (float)i0;
        int   e   = 2 * t - i0;                          // in [0, 6]
        float lo = sel7(g[2*k+8], g[2*k+7], g[2*k+6], g[2*k+5],
                        g[2*k+4], g[2*k+3], g[2*k+2], e);
        float hi = sel7(g[2*k+9], g[2*k+8], g[2*k+7], g[2*k+6],
                        g[2*k+5], g[2*k+4], g[2*k+3], e);
        dsv[k] = lo * (1.0f - w) + hi * w;
    }

    const int b  = row >> 6;
    const int ch = row & 63;
    float* o0 = out + ((size_t)b * 192 + ch) * LL + tbase;  // ds
    float* o1 = o0 + (size_t)64 * LL;                       // a
    float* o2 = o0 + (size_t)128 * LL;                      // d

    if (tbase + 3 < LL) {
        if ((row & 1) == 0) {
            // elem offset 8194*row + tbase == 0 mod 4 when row even -> 16B aligned
            __stcs((float4*)o0, make_float4(dsv[0], dsv[1], dsv[2], dsv[3]));
            __stcs((float4*)o1, make_float4(av[0],  av[1],  av[2],  av[3]));
            __stcs((float4*)o2, make_float4(dv[0],  dv[1],  dv[2],  dv[3]));
        } else {
            __stcs((float2*)o0,     make_float2(dsv[0], dsv[1]));
            __stcs((float2*)o0 + 1, make_float2(dsv[2], dsv[3]));
            __stcs((float2*)o1,     make_float2(av[0],  av[1]));
            __stcs((float2*)o1 + 1, make_float2(av[2],  av[3]));
            __stcs((float2*)o2,     make_float2(dv[0],  dv[1]));
            __stcs((float2*)o2 + 1, make_float2(dv[2],  dv[3]));
        }
    } else {
        #pragma unroll
        for (int k = 0; k < 4; k++) {
            if (tbase + k < LL) {
                o0[k] = dsv[k];
                o1[k] = av[k];
                o2[k] = dv[k];
            }
        }
    }
}

extern "C" void kernel_launch(void* const* d_in, const int* in_sizes, int n_in,
                              void* d_out, int out_size)
{
    const float* x = (const float*)d_in[0];
    float* out = (float*)d_out;
    dim3 grid(NTILES, 2048);
    dwt1d_fused_kernel<<<grid, THREADS>>>(x, out);
}